// round 2
// baseline (speedup 1.0000x reference)
#include <cuda_runtime.h>
#include <cstddef>

// CRF loss, B=512, N=1024, K=64.
// Forward recursion in exp-domain: s_j = sum_i exp(alpha_i - R) * E_ij,
// E = exp(trans) packed as f32x2 pairs in registers (one column per thread).
// 128-thread blocks carry 2 independent batches (fills all 4 SMSPs).
// Packed fma.rn.f32x2 halves FFMA instruction count.

#define KK 64
#define NN 1024
#define BB 512
#define GPB 2
#define TPB (KK * GPB)
#define L2E 1.4426950408889634f
#define LN2 0.6931471805599453f

typedef unsigned long long ull;

__device__ __forceinline__ float fast_ex2(float x) {
    float y; asm("ex2.approx.f32 %0, %1;" : "=f"(y) : "f"(x)); return y;
}
__device__ __forceinline__ float fast_lg2(float x) {
    float y; asm("lg2.approx.f32 %0, %1;" : "=f"(y) : "f"(x)); return y;
}
__device__ __forceinline__ void fma2(ull &d, ull a, ull b) {
    asm("fma.rn.f32x2 %0, %1, %2, %0;" : "+l"(d) : "l"(a), "l"(b));
}
__device__ __forceinline__ ull add2(ull a, ull b) {
    ull d; asm("add.rn.f32x2 %0, %1, %2;" : "=l"(d) : "l"(a), "l"(b)); return d;
}
__device__ __forceinline__ ull pack2(float lo, float hi) {
    ull d; asm("mov.b64 %0, {%1, %2};" : "=l"(d) : "f"(lo), "f"(hi)); return d;
}
__device__ __forceinline__ void unpack2(ull v, float &lo, float &hi) {
    asm("mov.b64 {%0, %1}, %2;" : "=f"(lo), "=f"(hi) : "l"(v));
}

__global__ __launch_bounds__(TPB) void crf_kernel(
    const float* __restrict__ y_pred,   // [B, N, K]
    const float* __restrict__ trans,    // [K, K]
    const int*   __restrict__ y_true,   // [B, N]
    float*       __restrict__ out)      // [B]
{
    const int g = threadIdx.x >> 6;          // batch group within block
    const int j = threadIdx.x & 63;          // state index
    const int b = blockIdx.x * GPB + g;

    __shared__ __align__(16) float aS[GPB][2][KK];
    __shared__ float refS[GPB][2];
    __shared__ int   flagS[GPB][2][2];
    __shared__ int   ytS[GPB][2][KK];
    __shared__ float red[GPB][KK];

    // Packed E column: E2[i] = (exp(trans[2i][j]), exp(trans[2i+1][j]))
    ull E2[KK / 2];
#pragma unroll
    for (int i = 0; i < KK / 2; i++) {
        float e0 = fast_ex2(trans[(2 * i) * KK + j] * L2E);
        float e1 = fast_ex2(trans[(2 * i + 1) * KK + j] * L2E);
        E2[i] = pack2(e0, e1);
    }

    const float* yp = y_pred + (size_t)b * NN * KK + j;
    const int* yt_row = y_true + b * NN;

    ytS[g][0][j] = yt_row[j];

    // ---- prologue: t = 0, emit pipeline depth 4 ----
    float e_cur = yp[0];
    float e_n1  = yp[(size_t)1 * KK];
    float e_n2  = yp[(size_t)2 * KK];
    float e_n3  = yp[(size_t)3 * KK];

    {
        bool ok = e_cur > -1000000.0f;
        unsigned bal = __ballot_sync(0xFFFFFFFFu, ok);
        if ((j & 31) == 0) flagS[g][0][j >> 5] = (bal == 0xFFFFFFFFu) ? 1 : 0;
    }
    __syncthreads();
    int m0 = flagS[g][0][0] & flagS[g][0][1];

    float alpha = m0 ? e_cur : 0.0f;
    float point = 0.0f, tsum = 0.0f;
    int yt_prev = ytS[g][0][0];
    if (m0 && j == yt_prev) point = e_cur;
    int m_prev = m0;
    float R = 0.0f;

    // shift pipeline to t=1
    e_cur = e_n1; e_n1 = e_n2; e_n2 = e_n3;
    e_n3 = yp[(size_t)4 * KK];

    int yt_pref = 0;

    // ---- main loop: t = 1 .. N-1 ----
    for (int t = 1; t < NN; ++t) {
        const int pb = t & 1;

        // Phase A (writes, pre-barrier)
        float aj = fast_ex2((alpha - R) * L2E);
        aS[g][pb][j] = aj;
        if (j == 0) refS[g][pb] = alpha;     // publish alpha_0 as next step's R

        bool okc = e_cur > -1000000.0f;
        unsigned bl = __ballot_sync(0xFFFFFFFFu, okc);
        if ((j & 31) == 0) flagS[g][pb][j >> 5] = (bl == 0xFFFFFFFFu) ? 1 : 0;

        if ((t & 63) == 1 && t < NN - 64) yt_pref = yt_row[(t & ~63) + 64 + j];
        if ((t & 63) == 48 && t < NN - 64) ytS[g][((t >> 6) + 1) & 1][j] = yt_pref;

        __syncthreads();

        // Phase B (reads, post-barrier)
        const int mm = flagS[g][pb][0] & flagS[g][pb][1];
        const float newR = refS[g][pb];

        const ulonglong2* a2 = (const ulonglong2*)aS[g][pb];
        ull acc0 = 0, acc1 = 0, acc2 = 0, acc3 = 0;
#pragma unroll
        for (int q = 0; q < 16; q += 2) {
            ulonglong2 v0 = a2[q];
            ulonglong2 v1 = a2[q + 1];
            fma2(acc0, v0.x, E2[2 * q + 0]);
            fma2(acc1, v0.y, E2[2 * q + 1]);
            fma2(acc2, v1.x, E2[2 * q + 2]);
            fma2(acc3, v1.y, E2[2 * q + 3]);
        }
        acc0 = add2(acc0, acc1);
        acc2 = add2(acc2, acc3);
        acc0 = add2(acc0, acc2);
        float slo, shi;
        unpack2(acc0, slo, shi);
        float s = slo + shi;

        float na = R + LN2 * fast_lg2(s) + e_cur;

        const int yt = ytS[g][(t >> 6) & 1][t & 63];
        if (mm) {
            alpha = na;
            if (j == yt) point += e_cur;
        }
        if (j == (t & 63) && (mm & m_prev)) tsum += __ldg(&trans[yt_prev * KK + yt]);

        R = newR;
        m_prev = mm;
        yt_prev = yt;

        // emit prefetch, distance 4
        e_cur = e_n1; e_n1 = e_n2; e_n2 = e_n3;
        e_n3 = (t + 4 < NN) ? yp[(size_t)(t + 4) * KK] : 0.0f;
    }

    // ---- epilogue ----
    red[g][j] = alpha;
    __syncthreads();
    if (j < 32) {
        float v = fmaxf(red[g][j], red[g][j + 32]);
#pragma unroll
        for (int o = 16; o > 0; o >>= 1)
            v = fmaxf(v, __shfl_xor_sync(0xFFFFFFFFu, v, o));
        if (j == 0) refS[g][0] = v;
    }
    __syncthreads();
    const float mx = refS[g][0];
    red[g][j] = fast_ex2((alpha - mx) * L2E);
    __syncthreads();
    if (j < 32) {
        float v = red[g][j] + red[g][j + 32];
#pragma unroll
        for (int o = 16; o > 0; o >>= 1)
            v += __shfl_xor_sync(0xFFFFFFFFu, v, o);
        if (j == 0) refS[g][0] = mx + LN2 * fast_lg2(v);   // log_norm
    }
    __syncthreads();
    red[g][j] = point + tsum;
    __syncthreads();
    if (j < 32) {
        float v = red[g][j] + red[g][j + 32];
#pragma unroll
        for (int o = 16; o > 0; o >>= 1)
            v += __shfl_xor_sync(0xFFFFFFFFu, v, o);
        if (j == 0) out[b] = refS[g][0] - v;
    }
}

extern "C" void kernel_launch(void* const* d_in, const int* in_sizes, int n_in,
                              void* d_out, int out_size) {
    const float* y_pred = (const float*)d_in[0];
    const float* trans  = (const float*)d_in[1];
    const int*   y_true = (const int*)d_in[2];
    float* out = (float*)d_out;
    crf_kernel<<<BB / GPB, TPB>>>(y_pred, trans, y_true, out);
}